// round 1
// baseline (speedup 1.0000x reference)
#include <cuda_runtime.h>
#include <math.h>

// Problem constants
#define DMODEL 1024
#define SEQ    2048
#define BATCH  2
#define MROWS  (BATCH*SEQ)   // 4096
#define NHEADS 16
#define HD     64
#define DFF    (4*DMODEL)    // 4096
#define EPS    1e-9f

// ---------------------------------------------------------------------------
// Scratch (device globals — no cudaMalloc allowed)
// ---------------------------------------------------------------------------
__device__ float g_xn  [MROWS*DMODEL]; // ln1 out, later ln2 out
__device__ float g_q   [MROWS*DMODEL];
__device__ float g_k   [MROWS*DMODEL];
__device__ float g_v   [MROWS*DMODEL];
__device__ float g_attn[MROWS*DMODEL]; // pre-out (concat heads)
__device__ float g_x1  [MROWS*DMODEL]; // x + attn_proj
__device__ float g_mid [MROWS*DFF];    // gelu(xn2 @ Wup^T)

// ---------------------------------------------------------------------------
// LayerNorm (torch-style unbiased variance, ddof=1)
// one block per row, 256 threads, 4 elems/thread
// ---------------------------------------------------------------------------
__global__ void ln_kernel(const float* __restrict__ x,
                          const float* __restrict__ mean_scale,
                          const float* __restrict__ std_scale,
                          float* __restrict__ out)
{
    int row = blockIdx.x;
    int t   = threadIdx.x;
    const float4* xr = (const float4*)(x + (size_t)row * DMODEL);
    float4 f = xr[t];

    float s  = f.x + f.y + f.z + f.w;
    float sq = f.x*f.x + f.y*f.y + f.z*f.z + f.w*f.w;

    // block reduction
    __shared__ float red_s[8], red_q[8];
    #pragma unroll
    for (int o = 16; o > 0; o >>= 1) {
        s  += __shfl_down_sync(0xffffffffu, s,  o);
        sq += __shfl_down_sync(0xffffffffu, sq, o);
    }
    int warp = t >> 5, lane = t & 31;
    if (lane == 0) { red_s[warp] = s; red_q[warp] = sq; }
    __syncthreads();
    if (warp == 0) {
        s  = red_s[lane & 7];
        sq = red_q[lane & 7];
        #pragma unroll
        for (int o = 4; o > 0; o >>= 1) {
            s  += __shfl_down_sync(0xffffffffu, s,  o);
            sq += __shfl_down_sync(0xffffffffu, sq, o);
        }
        if (lane == 0) { red_s[0] = s; red_q[0] = sq; }
    }
    __syncthreads();
    float mean = red_s[0] * (1.0f / DMODEL);
    float var  = (red_q[0] - DMODEL * mean * mean) * (1.0f / (DMODEL - 1));
    float rstd = rsqrtf(var + EPS);

    int d = t * 4;
    float4 ms = *(const float4*)(mean_scale + d);
    float4 ss = *(const float4*)(std_scale  + d);
    float4 o;
    o.x = (f.x - mean) * rstd * ss.x + ms.x;
    o.y = (f.y - mean) * rstd * ss.y + ms.y;
    o.z = (f.z - mean) * rstd * ss.z + ms.z;
    o.w = (f.w - mean) * rstd * ss.w + ms.w;
    *(float4*)(out + (size_t)row * DMODEL + d) = o;
}

// ---------------------------------------------------------------------------
// SGEMM: C[m,n] = epi( sum_k A[m,k]*B[n,k]  (+ R[m,n]) )
// A: MxK row-major, B: NxK row-major (both K-contiguous -> C = A @ B^T)
// tile 64x64, BK=16, 256 threads, 4x4 microtile
// EPI: 0 = none, 1 = exact gelu, 2 = residual add
// M,N multiples of 64; K multiple of 16 (holds for all calls here)
// ---------------------------------------------------------------------------
template<int EPI>
__global__ void __launch_bounds__(256)
gemm_kernel(const float* __restrict__ A, const float* __restrict__ Bw,
            const float* __restrict__ R, float* __restrict__ C,
            int M, int N, int K)
{
    __shared__ float As[16][68];
    __shared__ float Bs[16][68];

    const int bm = blockIdx.y * 64;
    const int bn = blockIdx.x * 64;
    const int tid = threadIdx.x;
    const int tx = tid & 15;       // 0..15 -> col group
    const int ty = tid >> 4;       // 0..15 -> row group
    const int lr = tid >> 2;       // 0..63  load row
    const int lk = (tid & 3) * 4;  // 0,4,8,12 load k-offset

    const float* Aptr = A + (size_t)(bm + lr) * K + lk;
    const float* Bptr = Bw + (size_t)(bn + lr) * K + lk;

    float acc[4][4];
    #pragma unroll
    for (int i = 0; i < 4; i++)
        #pragma unroll
        for (int j = 0; j < 4; j++) acc[i][j] = 0.f;

    for (int k0 = 0; k0 < K; k0 += 16) {
        float4 a = *(const float4*)(Aptr + k0);
        float4 b = *(const float4*)(Bptr + k0);
        As[lk+0][lr] = a.x; As[lk+1][lr] = a.y;
        As[lk+2][lr] = a.z; As[lk+3][lr] = a.w;
        Bs[lk+0][lr] = b.x; Bs[lk+1][lr] = b.y;
        Bs[lk+2][lr] = b.z; Bs[lk+3][lr] = b.w;
        __syncthreads();

        #pragma unroll
        for (int kk = 0; kk < 16; kk++) {
            float4 av = *(const float4*)&As[kk][ty * 4];
            float4 bv = *(const float4*)&Bs[kk][tx * 4];
            float ar[4] = {av.x, av.y, av.z, av.w};
            float br[4] = {bv.x, bv.y, bv.z, bv.w};
            #pragma unroll
            for (int i = 0; i < 4; i++)
                #pragma unroll
                for (int j = 0; j < 4; j++)
                    acc[i][j] += ar[i] * br[j];
        }
        __syncthreads();
    }

    // epilogue + store (float4 per row)
    #pragma unroll
    for (int i = 0; i < 4; i++) {
        int m = bm + ty * 4 + i;
        int n = bn + tx * 4;
        size_t idx = (size_t)m * N + n;
        float v[4];
        #pragma unroll
        for (int j = 0; j < 4; j++) {
            float val = acc[i][j];
            if (EPI == 1) {
                // exact GELU: 0.5*x*(1+erf(x/sqrt(2)))
                val = 0.5f * val * (1.0f + erff(val * 0.70710678118654752f));
            } else if (EPI == 2) {
                val += R[idx + j];
            }
            v[j] = val;
        }
        float4 o = {v[0], v[1], v[2], v[3]};
        *(float4*)(C + idx) = o;
    }
}

// ---------------------------------------------------------------------------
// Causal flash attention, fp32.
// grid: (SEQ/64 q-blocks, BATCH*NHEADS); block: 64 threads (1 q-row/thread)
// Q/K/V layout: [B, S, D] with D index = h*HD + d
// ---------------------------------------------------------------------------
__global__ void __launch_bounds__(64)
attn_kernel(const float* __restrict__ Q, const float* __restrict__ Km,
            const float* __restrict__ V, float* __restrict__ O)
{
    const int qb = blockIdx.x;
    const int bh = blockIdx.y;
    const int b  = bh / NHEADS, h = bh % NHEADS;
    const int t  = threadIdx.x;
    const int qrow = qb * 64 + t;

    const size_t headoff = (size_t)h * HD;
    const float* qptr = Q + ((size_t)(b * SEQ + qrow)) * DMODEL + headoff;

    float q[HD];
    #pragma unroll
    for (int d = 0; d < HD; d += 4) {
        float4 f = *(const float4*)(qptr + d);
        q[d] = f.x; q[d+1] = f.y; q[d+2] = f.z; q[d+3] = f.w;
    }

    float o[HD];
    #pragma unroll
    for (int d = 0; d < HD; d++) o[d] = 0.f;
    float mrun = -INFINITY, lrun = 0.f;

    __shared__ float4 Ks[64][HD/4];
    __shared__ float4 Vs[64][HD/4];

    for (int kb = 0; kb <= qb; kb++) {
        __syncthreads();
        {
            const float* kp = Km + ((size_t)(b * SEQ + kb * 64 + t)) * DMODEL + headoff;
            const float* vp = V  + ((size_t)(b * SEQ + kb * 64 + t)) * DMODEL + headoff;
            #pragma unroll
            for (int d = 0; d < HD/4; d++) {
                Ks[t][d] = *(const float4*)(kp + 4*d);
                Vs[t][d] = *(const float4*)(vp + 4*d);
            }
        }
        __syncthreads();

        const bool diag = (kb == qb);

        #pragma unroll 1
        for (int j0 = 0; j0 < 64; j0 += 16) {
            float sv[16];
            #pragma unroll
            for (int jj = 0; jj < 16; jj++) {
                float acc = 0.f;
                #pragma unroll
                for (int d4 = 0; d4 < HD/4; d4++) {
                    float4 kv = Ks[j0 + jj][d4];
                    acc += q[4*d4+0] * kv.x;
                    acc += q[4*d4+1] * kv.y;
                    acc += q[4*d4+2] * kv.z;
                    acc += q[4*d4+3] * kv.w;
                }
                acc *= 0.125f;  // 1/sqrt(64)
                if (diag && (kb * 64 + j0 + jj) > qrow) acc = -INFINITY;
                sv[jj] = acc;
            }
            float mloc = mrun;
            #pragma unroll
            for (int jj = 0; jj < 16; jj++) mloc = fmaxf(mloc, sv[jj]);
            if (mloc == -INFINITY) continue;   // whole chunk masked

            float scale = __expf(mrun - mloc); // mrun=-inf -> 0
            mrun = mloc;
            lrun *= scale;
            #pragma unroll
            for (int d = 0; d < HD; d++) o[d] *= scale;

            #pragma unroll
            for (int jj = 0; jj < 16; jj++) {
                float p = __expf(sv[jj] - mloc);
                lrun += p;
                #pragma unroll
                for (int d4 = 0; d4 < HD/4; d4++) {
                    float4 vv = Vs[j0 + jj][d4];
                    o[4*d4+0] += p * vv.x;
                    o[4*d4+1] += p * vv.y;
                    o[4*d4+2] += p * vv.z;
                    o[4*d4+3] += p * vv.w;
                }
            }
        }
    }

    float inv_l = 1.0f / lrun;
    float* optr = O + ((size_t)(b * SEQ + qrow)) * DMODEL + headoff;
    #pragma unroll
    for (int d = 0; d < HD; d += 4) {
        float4 f = {o[d] * inv_l, o[d+1] * inv_l, o[d+2] * inv_l, o[d+3] * inv_l};
        *(float4*)(optr + d) = f;
    }
}

// ---------------------------------------------------------------------------
// Launch
// ---------------------------------------------------------------------------
extern "C" void kernel_launch(void* const* d_in, const int* in_sizes, int n_in,
                              void* d_out, int out_size)
{
    const float* x       = (const float*)d_in[0];
    const float* Wq      = (const float*)d_in[1];
    const float* Wk      = (const float*)d_in[2];
    const float* Wv      = (const float*)d_in[3];
    const float* Wo      = (const float*)d_in[4];
    const float* W_up    = (const float*)d_in[5];
    const float* W_down  = (const float*)d_in[6];
    const float* ln1_ms  = (const float*)d_in[7];
    const float* ln1_ss  = (const float*)d_in[8];
    const float* ln2_ms  = (const float*)d_in[9];
    const float* ln2_ss  = (const float*)d_in[10];
    float* out = (float*)d_out;

    float *xn, *qb, *kb, *vb, *attn, *x1, *mid;
    cudaGetSymbolAddress((void**)&xn,   g_xn);
    cudaGetSymbolAddress((void**)&qb,   g_q);
    cudaGetSymbolAddress((void**)&kb,   g_k);
    cudaGetSymbolAddress((void**)&vb,   g_v);
    cudaGetSymbolAddress((void**)&attn, g_attn);
    cudaGetSymbolAddress((void**)&x1,   g_x1);
    cudaGetSymbolAddress((void**)&mid,  g_mid);

    // 1) LN1
    ln_kernel<<<MROWS, 256>>>(x, ln1_ms, ln1_ss, xn);

    // 2) Q,K,V projections (C = xn @ W^T)
    dim3 gqkv(DMODEL/64, MROWS/64);
    gemm_kernel<0><<<gqkv, 256>>>(xn, Wq, nullptr, qb, MROWS, DMODEL, DMODEL);
    gemm_kernel<0><<<gqkv, 256>>>(xn, Wk, nullptr, kb, MROWS, DMODEL, DMODEL);
    gemm_kernel<0><<<gqkv, 256>>>(xn, Wv, nullptr, vb, MROWS, DMODEL, DMODEL);

    // 3) causal attention -> pre-out (concat heads)
    attn_kernel<<<dim3(SEQ/64, BATCH*NHEADS), 64>>>(qb, kb, vb, attn);

    // 4) out projection + residual: x1 = x + attn @ Wo^T
    gemm_kernel<2><<<gqkv, 256>>>(attn, Wo, x, x1, MROWS, DMODEL, DMODEL);

    // 5) LN2
    ln_kernel<<<MROWS, 256>>>(x1, ln2_ms, ln2_ss, xn);

    // 6) MLP up + exact GELU: mid = gelu(xn @ W_up^T)
    dim3 gup(DFF/64, MROWS/64);
    gemm_kernel<1><<<gup, 256>>>(xn, W_up, nullptr, mid, MROWS, DFF, DMODEL);

    // 7) MLP down + residual: out = x1 + mid @ W_down^T
    dim3 gdown(DMODEL/64, MROWS/64);
    gemm_kernel<2><<<gdown, 256>>>(mid, W_down, x1, out, MROWS, DMODEL, DFF);
}

// round 4
// speedup vs baseline: 1.7210x; 1.7210x over previous
#include <cuda_runtime.h>
#include <cuda_bf16.h>
#include <math.h>
#include <stdint.h>

// Problem constants
#define DMODEL 1024
#define SEQ    2048
#define BATCH  2
#define MROWS  (BATCH*SEQ)   // 4096
#define NHEADS 16
#define HD     64
#define DFF    (4*DMODEL)    // 4096
#define EPS    1e-9f

// ---------------------------------------------------------------------------
// Scratch (device globals — no cudaMalloc allowed)
// ---------------------------------------------------------------------------
__device__ float g_xn  [MROWS*DMODEL];
__device__ float g_q   [MROWS*DMODEL];
__device__ float g_k   [MROWS*DMODEL];
__device__ float g_v   [MROWS*DMODEL];
__device__ float g_attn[MROWS*DMODEL];
__device__ float g_x1  [MROWS*DMODEL];
__device__ float g_mid [MROWS*DFF];

// ---------------------------------------------------------------------------
// helpers
// ---------------------------------------------------------------------------
__device__ __forceinline__ uint32_t smem_u32(const void* p) {
    uint32_t a;
    asm("{ .reg .u64 t; cvta.to.shared.u64 t, %1; cvt.u32.u64 %0, t; }" : "=r"(a) : "l"(p));
    return a;
}

__device__ __forceinline__ uint32_t packbf(float lo, float hi) {
    uint32_t r;
    asm("cvt.rn.bf16x2.f32 %0, %1, %2;" : "=r"(r) : "f"(hi), "f"(lo));
    return r;
}

__device__ __forceinline__ void ldsm4(uint32_t* r, uint32_t a) {
    asm volatile("ldmatrix.sync.aligned.m8n8.x4.shared.b16 {%0,%1,%2,%3}, [%4];"
                 : "=r"(r[0]), "=r"(r[1]), "=r"(r[2]), "=r"(r[3]) : "r"(a));
}
__device__ __forceinline__ void ldsm2(uint32_t* r, uint32_t a) {
    asm volatile("ldmatrix.sync.aligned.m8n8.x2.shared.b16 {%0,%1}, [%2];"
                 : "=r"(r[0]), "=r"(r[1]) : "r"(a));
}

__device__ __forceinline__ void mma16816(float* c, const uint32_t* a, const uint32_t* b) {
    asm volatile(
        "mma.sync.aligned.m16n8k16.row.col.f32.bf16.bf16.f32 "
        "{%0,%1,%2,%3}, {%4,%5,%6,%7}, {%8,%9}, {%0,%1,%2,%3};"
        : "+f"(c[0]), "+f"(c[1]), "+f"(c[2]), "+f"(c[3])
        : "r"(a[0]), "r"(a[1]), "r"(a[2]), "r"(a[3]), "r"(b[0]), "r"(b[1]));
}

// ---------------------------------------------------------------------------
// LayerNorm (unbiased variance, ddof=1)
// ---------------------------------------------------------------------------
__global__ void ln_kernel(const float* __restrict__ x,
                          const float* __restrict__ mean_scale,
                          const float* __restrict__ std_scale,
                          float* __restrict__ out)
{
    int row = blockIdx.x;
    int t   = threadIdx.x;
    const float4* xr = (const float4*)(x + (size_t)row * DMODEL);
    float4 f = xr[t];

    float s  = f.x + f.y + f.z + f.w;
    float sq = f.x*f.x + f.y*f.y + f.z*f.z + f.w*f.w;

    __shared__ float red_s[8], red_q[8];
    #pragma unroll
    for (int o = 16; o > 0; o >>= 1) {
        s  += __shfl_down_sync(0xffffffffu, s,  o);
        sq += __shfl_down_sync(0xffffffffu, sq, o);
    }
    int warp = t >> 5, lane = t & 31;
    if (lane == 0) { red_s[warp] = s; red_q[warp] = sq; }
    __syncthreads();
    if (warp == 0) {
        s  = red_s[lane & 7];
        sq = red_q[lane & 7];
        #pragma unroll
        for (int o = 4; o > 0; o >>= 1) {
            s  += __shfl_down_sync(0xffffffffu, s,  o);
            sq += __shfl_down_sync(0xffffffffu, sq, o);
        }
        if (lane == 0) { red_s[0] = s; red_q[0] = sq; }
    }
    __syncthreads();
    float mean = red_s[0] * (1.0f / DMODEL);
    float var  = (red_q[0] - DMODEL * mean * mean) * (1.0f / (DMODEL - 1));
    float rstd = rsqrtf(var + EPS);

    int d = t * 4;
    float4 ms = *(const float4*)(mean_scale + d);
    float4 ss = *(const float4*)(std_scale  + d);
    float4 o;
    o.x = (f.x - mean) * rstd * ss.x + ms.x;
    o.y = (f.y - mean) * rstd * ss.y + ms.y;
    o.z = (f.z - mean) * rstd * ss.z + ms.z;
    o.w = (f.w - mean) * rstd * ss.w + ms.w;
    *(float4*)(out + (size_t)row * DMODEL + d) = o;
}

// ---------------------------------------------------------------------------
// HMMA bf16 split GEMM:  C[m,n] = epi( sum_k A[m,k]*B[n,k] (+R[m,n]) )
// A: MxK fp32 row-major, B: NxK fp32 row-major (both K-contiguous)
// 3-term bf16 split: AhBh + AlBh + AhBl, fp32 accumulate.
// CTA 128x128, BK=32, 256 threads (8 warps, warp tile 64x32).
// EPI: 0 none, 1 exact gelu, 2 residual add.
// Requires M%128==0, N%128==0, K%32==0.
// ---------------------------------------------------------------------------
template<int EPI>
__global__ void __launch_bounds__(256)
gemm_mma(const float* __restrict__ A, const float* __restrict__ B,
         const float* __restrict__ R, float* __restrict__ C,
         int M, int N, int K)
{
    // smem planes: [row 0..127][k 0..31] bf16, row = 64B, XOR-swizzled
    __shared__ __align__(16) uint8_t sAh[128*64];
    __shared__ __align__(16) uint8_t sAl[128*64];
    __shared__ __align__(16) uint8_t sBh[128*64];
    __shared__ __align__(16) uint8_t sBl[128*64];

    const int t    = threadIdx.x;
    const int w    = t >> 5;
    const int lane = t & 31;
    const int bm   = blockIdx.y * 128;
    const int bn   = blockIdx.x * 128;

    const uint32_t uAh = smem_u32(sAh), uAl = smem_u32(sAl);
    const uint32_t uBh = smem_u32(sBh), uBl = smem_u32(sBl);

    float acc[4][4][4];
    #pragma unroll
    for (int i = 0; i < 4; i++)
        #pragma unroll
        for (int j = 0; j < 4; j++)
            #pragma unroll
            for (int c = 0; c < 4; c++) acc[i][j][c] = 0.f;

    // loader mapping: thread t -> row = t>>1 (0..127), k-half = (t&1)*16
    const int lrow = t >> 1;
    const int lkh  = (t & 1) * 16;
    const uint32_t wrow = (uint32_t)lrow * 64;
    const uint32_t xs   = (uint32_t)(((lrow >> 1) & 3) << 4);
    const float* Ag = A + (size_t)(bm + lrow) * K + lkh;
    const float* Bg = B + (size_t)(bn + lrow) * K + lkh;

    // ldmatrix addressing
    const int wm0 = (w >> 2) * 64;     // warp M origin within tile
    const int wn0 = (w & 3) * 32;      // warp N origin
    const int amrel = lane & 15;
    const uint32_t akb = (uint32_t)((lane >> 4) * 16);   // byte offset of k-chunk
    const int bnrel = lane & 7;
    const uint32_t bkb = (uint32_t)(((lane >> 3) & 1) * 16);

    uint32_t aBaseH[4], aBaseL[4], aXm[4];
    #pragma unroll
    for (int i = 0; i < 4; i++) {
        int m = wm0 + i * 16 + amrel;
        aBaseH[i] = uAh + (uint32_t)m * 64;
        aBaseL[i] = uAl + (uint32_t)m * 64;
        aXm[i]    = (uint32_t)(((m >> 1) & 3) << 4);
    }
    uint32_t bBaseH[4], bBaseL[4], bXm[4];
    #pragma unroll
    for (int j = 0; j < 4; j++) {
        int n = wn0 + j * 8 + bnrel;
        bBaseH[j] = uBh + (uint32_t)n * 64;
        bBaseL[j] = uBl + (uint32_t)n * 64;
        bXm[j]    = (uint32_t)(((n >> 1) & 3) << 4);
    }

    for (int kt = 0; kt < K; kt += 32) {
        __syncthreads();   // previous compute done before overwrite
        #pragma unroll
        for (int q = 0; q < 4; q++) {
            int kk = lkh + 4 * q;          // 0..28
            uint32_t off = wrow + (((uint32_t)(2 * kk)) ^ xs);

            float4 va = *(const float4*)(Ag + kt + 4 * q);
            __nv_bfloat16 h0 = __float2bfloat16_rn(va.x);
            __nv_bfloat16 h1 = __float2bfloat16_rn(va.y);
            __nv_bfloat16 h2 = __float2bfloat16_rn(va.z);
            __nv_bfloat16 h3 = __float2bfloat16_rn(va.w);
            uint2 ph = { (uint32_t)__bfloat16_as_ushort(h0) |
                         ((uint32_t)__bfloat16_as_ushort(h1) << 16),
                         (uint32_t)__bfloat16_as_ushort(h2) |
                         ((uint32_t)__bfloat16_as_ushort(h3) << 16) };
            uint2 pl = { packbf(va.x - __bfloat162float(h0), va.y - __bfloat162float(h1)),
                         packbf(va.z - __bfloat162float(h2), va.w - __bfloat162float(h3)) };
            *(uint2*)(sAh + off) = ph;
            *(uint2*)(sAl + off) = pl;

            float4 vb = *(const float4*)(Bg + kt + 4 * q);
            __nv_bfloat16 g0 = __float2bfloat16_rn(vb.x);
            __nv_bfloat16 g1 = __float2bfloat16_rn(vb.y);
            __nv_bfloat16 g2 = __float2bfloat16_rn(vb.z);
            __nv_bfloat16 g3 = __float2bfloat16_rn(vb.w);
            uint2 qh = { (uint32_t)__bfloat16_as_ushort(g0) |
                         ((uint32_t)__bfloat16_as_ushort(g1) << 16),
                         (uint32_t)__bfloat16_as_ushort(g2) |
                         ((uint32_t)__bfloat16_as_ushort(g3) << 16) };
            uint2 ql = { packbf(vb.x - __bfloat162float(g0), vb.y - __bfloat162float(g1)),
                         packbf(vb.z - __bfloat162float(g2), vb.w - __bfloat162float(g3)) };
            *(uint2*)(sBh + off) = qh;
            *(uint2*)(sBl + off) = ql;
        }
        __syncthreads();

        #pragma unroll
        for (int s = 0; s < 2; s++) {
            const uint32_t koffA = (uint32_t)(32 * s) + akb;
            const uint32_t koffB = (uint32_t)(32 * s) + bkb;

            uint32_t ah[4][4], al[4][4], bh[4][2], bl[4][2];
            #pragma unroll
            for (int i = 0; i < 4; i++) {
                ldsm4(ah[i], aBaseH[i] + (koffA ^ aXm[i]));
                ldsm4(al[i], aBaseL[i] + (koffA ^ aXm[i]));
            }
            #pragma unroll
            for (int j = 0; j < 4; j++) {
                ldsm2(bh[j], bBaseH[j] + (koffB ^ bXm[j]));
                ldsm2(bl[j], bBaseL[j] + (koffB ^ bXm[j]));
            }
            #pragma unroll
            for (int i = 0; i < 4; i++)
                #pragma unroll
                for (int j = 0; j < 4; j++) {
                    mma16816(acc[i][j], ah[i], bh[j]);
                    mma16816(acc[i][j], al[i], bh[j]);
                    mma16816(acc[i][j], ah[i], bl[j]);
                }
        }
    }

    // epilogue
    const int g  = lane >> 2;
    const int tt = lane & 3;
    #pragma unroll
    for (int i = 0; i < 4; i++) {
        #pragma unroll
        for (int j = 0; j < 4; j++) {
            int m0r = bm + wm0 + i * 16 + g;
            int nn  = bn + wn0 + j * 8 + 2 * tt;
            float v[4] = {acc[i][j][0], acc[i][j][1], acc[i][j][2], acc[i][j][3]};
            if (EPI == 1) {
                #pragma unroll
                for (int c = 0; c < 4; c++)
                    v[c] = 0.5f * v[c] * (1.0f + erff(v[c] * 0.70710678118654752f));
            } else if (EPI == 2) {
                float2 r0 = *(const float2*)(R + (size_t)m0r * N + nn);
                float2 r1 = *(const float2*)(R + (size_t)(m0r + 8) * N + nn);
                v[0] += r0.x; v[1] += r0.y; v[2] += r1.x; v[3] += r1.y;
            }
            float2 o0 = {v[0], v[1]};
            float2 o1 = {v[2], v[3]};
            *(float2*)(C + (size_t)m0r * N + nn) = o0;
            *(float2*)(C + (size_t)(m0r + 8) * N + nn) = o1;
        }
    }
}

// ---------------------------------------------------------------------------
// Causal flash attention, fp32
// ---------------------------------------------------------------------------
__global__ void __launch_bounds__(64)
attn_kernel(const float* __restrict__ Q, const float* __restrict__ Km,
            const float* __restrict__ V, float* __restrict__ O)
{
    const int qb = blockIdx.x;
    const int bh = blockIdx.y;
    const int b  = bh / NHEADS, h = bh % NHEADS;
    const int t  = threadIdx.x;
    const int qrow = qb * 64 + t;

    const size_t headoff = (size_t)h * HD;
    const float* qptr = Q + ((size_t)(b * SEQ + qrow)) * DMODEL + headoff;

    float q[HD];
    #pragma unroll
    for (int d = 0; d < HD; d += 4) {
        float4 f = *(const float4*)(qptr + d);
        q[d] = f.x; q[d+1] = f.y; q[d+2] = f.z; q[d+3] = f.w;
    }

    float o[HD];
    #pragma unroll
    for (int d = 0; d < HD; d++) o[d] = 0.f;
    float mrun = -INFINITY, lrun = 0.f;

    __shared__ float4 Ks[64][HD/4];
    __shared__ float4 Vs[64][HD/4];

    for (int kb = 0; kb <= qb; kb++) {
        __syncthreads();
        {
            const float* kp = Km + ((size_t)(b * SEQ + kb * 64 + t)) * DMODEL + headoff;
            const float* vp = V  + ((size_t)(b * SEQ + kb * 64 + t)) * DMODEL + headoff;
            #pragma unroll
            for (int d = 0; d < HD/4; d++) {
                Ks[t][d] = *(const float4*)(kp + 4*d);
                Vs[t][d] = *(const float4*)(vp + 4*d);
            }
        }
        __syncthreads();

        const bool diag = (kb == qb);

        #pragma unroll 1
        for (int j0 = 0; j0 < 64; j0 += 16) {
            float sv[16];
            #pragma unroll
            for (int jj = 0; jj < 16; jj++) {
                float acc = 0.f;
                #pragma unroll
                for (int d4 = 0; d4 < HD/4; d4++) {
                    float4 kv = Ks[j0 + jj][d4];
                    acc += q[4*d4+0] * kv.x;
                    acc += q[4*d4+1] * kv.y;
                    acc += q[4*d4+2] * kv.z;
                    acc += q[4*d4+3] * kv.w;
                }
                acc *= 0.125f;
                if (diag && (kb * 64 + j0 + jj) > qrow) acc = -INFINITY;
                sv[jj] = acc;
            }
            float mloc = mrun;
            #pragma unroll
            for (int jj = 0; jj < 16; jj++) mloc = fmaxf(mloc, sv[jj]);
            if (mloc == -INFINITY) continue;

            float scale = __expf(mrun - mloc);
            mrun = mloc;
            lrun *= scale;
            #pragma unroll
            for (int d = 0; d < HD; d++) o[d] *= scale;

            #pragma unroll
            for (int jj = 0; jj < 16; jj++) {
                float p = __expf(sv[jj] - mloc);
                lrun += p;
                #pragma unroll
                for (int d4 = 0; d4 < HD/4; d4++) {
                    float4 vv = Vs[j0 + jj][d4];
                    o[4*d4+0] += p * vv.x;
                    o[4*d4+1] += p * vv.y;
                    o[4*d4+2] += p * vv.z;
                    o[4*d4+3] += p * vv.w;
                }
            }
        }
    }

    float inv_l = 1.0f / lrun;
    float* optr = O + ((size_t)(b * SEQ + qrow)) * DMODEL + headoff;
    #pragma unroll
    for (int d = 0; d < HD; d += 4) {
        float4 f = {o[d] * inv_l, o[d+1] * inv_l, o[d+2] * inv_l, o[d+3] * inv_l};
        *(float4*)(optr + d) = f;
    }
}

// ---------------------------------------------------------------------------
// Launch
// ---------------------------------------------------------------------------
extern "C" void kernel_launch(void* const* d_in, const int* in_sizes, int n_in,
                              void* d_out, int out_size)
{
    const float* x       = (const float*)d_in[0];
    const float* Wq      = (const float*)d_in[1];
    const float* Wk      = (const float*)d_in[2];
    const float* Wv      = (const float*)d_in[3];
    const float* Wo      = (const float*)d_in[4];
    const float* W_up    = (const float*)d_in[5];
    const float* W_down  = (const float*)d_in[6];
    const float* ln1_ms  = (const float*)d_in[7];
    const float* ln1_ss  = (const float*)d_in[8];
    const float* ln2_ms  = (const float*)d_in[9];
    const float* ln2_ss  = (const float*)d_in[10];
    float* out = (float*)d_out;

    float *xn, *qb, *kb, *vb, *attn, *x1, *mid;
    cudaGetSymbolAddress((void**)&xn,   g_xn);
    cudaGetSymbolAddress((void**)&qb,   g_q);
    cudaGetSymbolAddress((void**)&kb,   g_k);
    cudaGetSymbolAddress((void**)&vb,   g_v);
    cudaGetSymbolAddress((void**)&attn, g_attn);
    cudaGetSymbolAddress((void**)&x1,   g_x1);
    cudaGetSymbolAddress((void**)&mid,  g_mid);

    // 1) LN1
    ln_kernel<<<MROWS, 256>>>(x, ln1_ms, ln1_ss, xn);

    // 2) Q,K,V projections
    dim3 gqkv(DMODEL / 128, MROWS / 128);
    gemm_mma<0><<<gqkv, 256>>>(xn, Wq, nullptr, qb, MROWS, DMODEL, DMODEL);
    gemm_mma<0><<<gqkv, 256>>>(xn, Wk, nullptr, kb, MROWS, DMODEL, DMODEL);
    gemm_mma<0><<<gqkv, 256>>>(xn, Wv, nullptr, vb, MROWS, DMODEL, DMODEL);

    // 3) causal attention
    attn_kernel<<<dim3(SEQ / 64, BATCH * NHEADS), 64>>>(qb, kb, vb, attn);

    // 4) out projection + residual
    gemm_mma<2><<<gqkv, 256>>>(attn, Wo, x, x1, MROWS, DMODEL, DMODEL);

    // 5) LN2
    ln_kernel<<<MROWS, 256>>>(x1, ln2_ms, ln2_ss, xn);

    // 6) MLP up + exact gelu
    dim3 gup(DFF / 128, MROWS / 128);
    gemm_mma<1><<<gup, 256>>>(xn, W_up, nullptr, mid, MROWS, DFF, DMODEL);

    // 7) MLP down + residual
    dim3 gdown(DMODEL / 128, MROWS / 128);
    gemm_mma<2><<<gdown, 256>>>(mid, W_down, x1, out, MROWS, DMODEL, DFF);
}

// round 7
// speedup vs baseline: 3.0201x; 1.7549x over previous
#include <cuda_runtime.h>
#include <cuda_bf16.h>
#include <cuda_fp16.h>
#include <math.h>
#include <stdint.h>

// Problem constants
#define DMODEL 1024
#define SEQ    2048
#define BATCH  2
#define MROWS  (BATCH*SEQ)   // 4096
#define NHEADS 16
#define HD     64
#define DFF    (4*DMODEL)    // 4096
#define EPS    1e-9f

// ---------------------------------------------------------------------------
// Scratch (device globals — no cudaMalloc allowed)
// ---------------------------------------------------------------------------
__device__ float g_xn  [MROWS*DMODEL];
__device__ float g_q   [MROWS*DMODEL];
__device__ float g_k   [MROWS*DMODEL];
__device__ float g_v   [MROWS*DMODEL];
__device__ float g_attn[MROWS*DMODEL];
__device__ float g_x1  [MROWS*DMODEL];
__device__ float g_mid [MROWS*DFF];

// ---------------------------------------------------------------------------
// helpers
// ---------------------------------------------------------------------------
__device__ __forceinline__ uint32_t smem_u32(const void* p) {
    uint32_t a;
    asm("{ .reg .u64 t; cvta.to.shared.u64 t, %1; cvt.u32.u64 %0, t; }" : "=r"(a) : "l"(p));
    return a;
}

__device__ __forceinline__ uint32_t packbf(float lo, float hi) {
    uint32_t r;
    asm("cvt.rn.bf16x2.f32 %0, %1, %2;" : "=r"(r) : "f"(hi), "f"(lo));
    return r;
}

__device__ __forceinline__ uint32_t packhf(float lo, float hi) {
    __half2 h = __floats2half2_rn(lo, hi);
    return *(uint32_t*)&h;
}

__device__ __forceinline__ void ldsm4(uint32_t* r, uint32_t a) {
    asm volatile("ldmatrix.sync.aligned.m8n8.x4.shared.b16 {%0,%1,%2,%3}, [%4];"
                 : "=r"(r[0]), "=r"(r[1]), "=r"(r[2]), "=r"(r[3]) : "r"(a));
}
__device__ __forceinline__ void ldsm2(uint32_t* r, uint32_t a) {
    asm volatile("ldmatrix.sync.aligned.m8n8.x2.shared.b16 {%0,%1}, [%2];"
                 : "=r"(r[0]), "=r"(r[1]) : "r"(a));
}
__device__ __forceinline__ void ldsm4t(uint32_t* r, uint32_t a) {
    asm volatile("ldmatrix.sync.aligned.m8n8.x4.trans.shared.b16 {%0,%1,%2,%3}, [%4];"
                 : "=r"(r[0]), "=r"(r[1]), "=r"(r[2]), "=r"(r[3]) : "r"(a));
}

__device__ __forceinline__ void mma_bf(float* c, const uint32_t* a, const uint32_t* b) {
    asm volatile(
        "mma.sync.aligned.m16n8k16.row.col.f32.bf16.bf16.f32 "
        "{%0,%1,%2,%3}, {%4,%5,%6,%7}, {%8,%9}, {%0,%1,%2,%3};"
        : "+f"(c[0]), "+f"(c[1]), "+f"(c[2]), "+f"(c[3])
        : "r"(a[0]), "r"(a[1]), "r"(a[2]), "r"(a[3]), "r"(b[0]), "r"(b[1]));
}

__device__ __forceinline__ void mma_hf(float* c, const uint32_t* a, const uint32_t* b) {
    asm volatile(
        "mma.sync.aligned.m16n8k16.row.col.f32.f16.f16.f32 "
        "{%0,%1,%2,%3}, {%4,%5,%6,%7}, {%8,%9}, {%0,%1,%2,%3};"
        : "+f"(c[0]), "+f"(c[1]), "+f"(c[2]), "+f"(c[3])
        : "r"(a[0]), "r"(a[1]), "r"(a[2]), "r"(a[3]), "r"(b[0]), "r"(b[1]));
}

// ---------------------------------------------------------------------------
// LayerNorm (unbiased variance, ddof=1)
// ---------------------------------------------------------------------------
__global__ void ln_kernel(const float* __restrict__ x,
                          const float* __restrict__ mean_scale,
                          const float* __restrict__ std_scale,
                          float* __restrict__ out)
{
    int row = blockIdx.x;
    int t   = threadIdx.x;
    const float4* xr = (const float4*)(x + (size_t)row * DMODEL);
    float4 f = xr[t];

    float s  = f.x + f.y + f.z + f.w;
    float sq = f.x*f.x + f.y*f.y + f.z*f.z + f.w*f.w;

    __shared__ float red_s[8], red_q[8];
    #pragma unroll
    for (int o = 16; o > 0; o >>= 1) {
        s  += __shfl_down_sync(0xffffffffu, s,  o);
        sq += __shfl_down_sync(0xffffffffu, sq, o);
    }
    int warp = t >> 5, lane = t & 31;
    if (lane == 0) { red_s[warp] = s; red_q[warp] = sq; }
    __syncthreads();
    if (warp == 0) {
        s  = red_s[lane & 7];
        sq = red_q[lane & 7];
        #pragma unroll
        for (int o = 4; o > 0; o >>= 1) {
            s  += __shfl_down_sync(0xffffffffu, s,  o);
            sq += __shfl_down_sync(0xffffffffu, sq, o);
        }
        if (lane == 0) { red_s[0] = s; red_q[0] = sq; }
    }
    __syncthreads();
    float mean = red_s[0] * (1.0f / DMODEL);
    float var  = (red_q[0] - DMODEL * mean * mean) * (1.0f / (DMODEL - 1));
    float rstd = rsqrtf(var + EPS);

    int d = t * 4;
    float4 ms = *(const float4*)(mean_scale + d);
    float4 ss = *(const float4*)(std_scale  + d);
    float4 o;
    o.x = (f.x - mean) * rstd * ss.x + ms.x;
    o.y = (f.y - mean) * rstd * ss.y + ms.y;
    o.z = (f.z - mean) * rstd * ss.z + ms.z;
    o.w = (f.w - mean) * rstd * ss.w + ms.w;
    *(float4*)(out + (size_t)row * DMODEL + d) = o;
}

// ---------------------------------------------------------------------------
// HMMA bf16 3-term split GEMM, double-buffered smem + register prefetch.
// C[m,n] = epi( sum_k A[m,k]*B[n,k] (+R[m,n]) )
// CTA 128x128, BK=32, 256 threads (8 warps, warp tile 64x32).
// Dynamic smem: 2 stages x 4 planes x 8KB = 64KB.
// ---------------------------------------------------------------------------
#define GSTG 8192

template<int EPI>
__global__ void __launch_bounds__(256)
gemm_mma(const float* __restrict__ A, const float* __restrict__ B,
         const float* __restrict__ R, float* __restrict__ C,
         int M, int N, int K)
{
    extern __shared__ __align__(16) uint8_t dsm[];
    uint8_t* sAh = dsm;                 // [2][8192]
    uint8_t* sAl = dsm + 2*GSTG;
    uint8_t* sBh = dsm + 4*GSTG;
    uint8_t* sBl = dsm + 6*GSTG;

    const int t    = threadIdx.x;
    const int w    = t >> 5;
    const int lane = t & 31;
    const int bm   = blockIdx.y * 128;
    const int bn   = blockIdx.x * 128;

    const uint32_t uAh = smem_u32(sAh), uAl = smem_u32(sAl);
    const uint32_t uBh = smem_u32(sBh), uBl = smem_u32(sBl);

    float acc[4][4][4];
    #pragma unroll
    for (int i = 0; i < 4; i++)
        #pragma unroll
        for (int j = 0; j < 4; j++)
            #pragma unroll
            for (int c = 0; c < 4; c++) acc[i][j][c] = 0.f;

    // loader mapping: thread t -> row = t>>1 (0..127), k-half = (t&1)*16
    const int lrow = t >> 1;
    const int lkh  = (t & 1) * 16;
    const uint32_t wrow = (uint32_t)lrow * 64;
    const uint32_t xs   = (uint32_t)(((lrow >> 1) & 3) << 4);
    const float* Ag = A + (size_t)(bm + lrow) * K + lkh;
    const float* Bg = B + (size_t)(bn + lrow) * K + lkh;

    // ldmatrix addressing
    const int wm0 = (w >> 2) * 64;
    const int wn0 = (w & 3) * 32;
    const int amrel = lane & 15;
    const uint32_t akb = (uint32_t)((lane >> 4) * 16);
    const int bnrel = lane & 7;
    const uint32_t bkb = (uint32_t)(((lane >> 3) & 1) * 16);

    uint32_t aBaseH[4], aBaseL[4], aXm[4];
    #pragma unroll
    for (int i = 0; i < 4; i++) {
        int m = wm0 + i * 16 + amrel;
        aBaseH[i] = uAh + (uint32_t)m * 64;
        aBaseL[i] = uAl + (uint32_t)m * 64;
        aXm[i]    = (uint32_t)(((m >> 1) & 3) << 4);
    }
    uint32_t bBaseH[4], bBaseL[4], bXm[4];
    #pragma unroll
    for (int j = 0; j < 4; j++) {
        int n = wn0 + j * 8 + bnrel;
        bBaseH[j] = uBh + (uint32_t)n * 64;
        bBaseL[j] = uBl + (uint32_t)n * 64;
        bXm[j]    = (uint32_t)(((n >> 1) & 3) << 4);
    }

    // prefetch tile kt=0
    float4 pa[4], pb[4];
    #pragma unroll
    for (int q = 0; q < 4; q++) {
        pa[q] = *(const float4*)(Ag + 4 * q);
        pb[q] = *(const float4*)(Bg + 4 * q);
    }

    uint32_t p = 0;
    for (int kt = 0; kt < K; kt += 32) {
        const uint32_t so = p * GSTG;
        // convert + store stage p
        #pragma unroll
        for (int q = 0; q < 4; q++) {
            int kk = lkh + 4 * q;
            uint32_t off = so + wrow + (((uint32_t)(2 * kk)) ^ xs);

            float4 va = pa[q];
            __nv_bfloat16 h0 = __float2bfloat16_rn(va.x);
            __nv_bfloat16 h1 = __float2bfloat16_rn(va.y);
            __nv_bfloat16 h2 = __float2bfloat16_rn(va.z);
            __nv_bfloat16 h3 = __float2bfloat16_rn(va.w);
            uint2 ph = { (uint32_t)__bfloat16_as_ushort(h0) |
                         ((uint32_t)__bfloat16_as_ushort(h1) << 16),
                         (uint32_t)__bfloat16_as_ushort(h2) |
                         ((uint32_t)__bfloat16_as_ushort(h3) << 16) };
            uint2 pl = { packbf(va.x - __bfloat162float(h0), va.y - __bfloat162float(h1)),
                         packbf(va.z - __bfloat162float(h2), va.w - __bfloat162float(h3)) };
            *(uint2*)(sAh + off) = ph;
            *(uint2*)(sAl + off) = pl;

            float4 vb = pb[q];
            __nv_bfloat16 g0 = __float2bfloat16_rn(vb.x);
            __nv_bfloat16 g1 = __float2bfloat16_rn(vb.y);
            __nv_bfloat16 g2 = __float2bfloat16_rn(vb.z);
            __nv_bfloat16 g3 = __float2bfloat16_rn(vb.w);
            uint2 qh = { (uint32_t)__bfloat16_as_ushort(g0) |
                         ((uint32_t)__bfloat16_as_ushort(g1) << 16),
                         (uint32_t)__bfloat16_as_ushort(g2) |
                         ((uint32_t)__bfloat16_as_ushort(g3) << 16) };
            uint2 ql = { packbf(vb.x - __bfloat162float(g0), vb.y - __bfloat162float(g1)),
                         packbf(vb.z - __bfloat162float(g2), vb.w - __bfloat162float(g3)) };
            *(uint2*)(sBh + off) = qh;
            *(uint2*)(sBl + off) = ql;
        }
        // prefetch next tile (LDG issued before the sync; hidden by compute)
        if (kt + 32 < K) {
            #pragma unroll
            for (int q = 0; q < 4; q++) {
                pa[q] = *(const float4*)(Ag + kt + 32 + 4 * q);
                pb[q] = *(const float4*)(Bg + kt + 32 + 4 * q);
            }
        }
        __syncthreads();

        #pragma unroll
        for (int s = 0; s < 2; s++) {
            const uint32_t koffA = (uint32_t)(32 * s) + akb;
            const uint32_t koffB = (uint32_t)(32 * s) + bkb;

            uint32_t ah[4][4], al[4][4], bh[4][2], bl[4][2];
            #pragma unroll
            for (int i = 0; i < 4; i++) {
                ldsm4(ah[i], aBaseH[i] + so + (koffA ^ aXm[i]));
                ldsm4(al[i], aBaseL[i] + so + (koffA ^ aXm[i]));
            }
            #pragma unroll
            for (int j = 0; j < 4; j++) {
                ldsm2(bh[j], bBaseH[j] + so + (koffB ^ bXm[j]));
                ldsm2(bl[j], bBaseL[j] + so + (koffB ^ bXm[j]));
            }
            #pragma unroll
            for (int i = 0; i < 4; i++)
                #pragma unroll
                for (int j = 0; j < 4; j++) {
                    mma_bf(acc[i][j], ah[i], bh[j]);
                    mma_bf(acc[i][j], al[i], bh[j]);
                    mma_bf(acc[i][j], ah[i], bl[j]);
                }
        }
        p ^= 1;
    }

    // epilogue
    const int g  = lane >> 2;
    const int tt = lane & 3;
    #pragma unroll
    for (int i = 0; i < 4; i++) {
        #pragma unroll
        for (int j = 0; j < 4; j++) {
            int m0r = bm + wm0 + i * 16 + g;
            int nn  = bn + wn0 + j * 8 + 2 * tt;
            float v[4] = {acc[i][j][0], acc[i][j][1], acc[i][j][2], acc[i][j][3]};
            if (EPI == 1) {
                #pragma unroll
                for (int c = 0; c < 4; c++)
                    v[c] = 0.5f * v[c] * (1.0f + erff(v[c] * 0.70710678118654752f));
            } else if (EPI == 2) {
                float2 r0 = *(const float2*)(R + (size_t)m0r * N + nn);
                float2 r1 = *(const float2*)(R + (size_t)(m0r + 8) * N + nn);
                v[0] += r0.x; v[1] += r0.y; v[2] += r1.x; v[3] += r1.y;
            }
            float2 o0 = {v[0], v[1]};
            float2 o1 = {v[2], v[3]};
            *(float2*)(C + (size_t)m0r * N + nn) = o0;
            *(float2*)(C + (size_t)(m0r + 8) * N + nn) = o1;
        }
    }
}

// ---------------------------------------------------------------------------
// Causal flash attention, fp16 HMMA.
// grid: (SEQ/64 qblocks [reversed], BATCH*NHEADS), 128 threads (4 warps).
// Each warp owns 16 q rows. kv tiles of 64.
// ---------------------------------------------------------------------------
__global__ void __launch_bounds__(128)
attn_mma(const float* __restrict__ Qp, const float* __restrict__ Kp,
         const float* __restrict__ Vp, float* __restrict__ Op)
{
    __shared__ __align__(16) uint8_t sQ[64 * 128];
    __shared__ __align__(16) uint8_t sK[64 * 128];
    __shared__ __align__(16) uint8_t sV[64 * 128];

    const int qb = (int)gridDim.x - 1 - (int)blockIdx.x;  // big blocks first
    const int bh = blockIdx.y;
    const int b  = bh >> 4, h = bh & 15;
    const int t  = threadIdx.x;
    const int w  = t >> 5;
    const int lane = t & 31;
    const int q0 = qb * 64;
    const size_t hoff = (size_t)h * HD;

    const uint32_t uQ = smem_u32(sQ), uK = smem_u32(sK), uV = smem_u32(sV);

    // ---- load Q tile (scaled by 1/8), fp32 -> fp16, swizzled rows of 128B
    {
        int row = t >> 1;
        int cs  = (t & 1) * 4;   // 16B-chunk start (each chunk = 8 fp16 cols)
        const float* src = Qp + ((size_t)(b * SEQ + q0 + row)) * DMODEL + hoff + cs * 8;
        uint32_t swz = (uint32_t)((row & 7) << 4);
        #pragma unroll
        for (int c = 0; c < 4; c++) {
            float4 f0 = *(const float4*)(src + c * 8);
            float4 f1 = *(const float4*)(src + c * 8 + 4);
            uint4 u = { packhf(f0.x * 0.125f, f0.y * 0.125f),
                        packhf(f0.z * 0.125f, f0.w * 0.125f),
                        packhf(f1.x * 0.125f, f1.y * 0.125f),
                        packhf(f1.z * 0.125f, f1.w * 0.125f) };
            *(uint4*)(sQ + row * 128 + ((uint32_t)((cs + c) * 16) ^ swz)) = u;
        }
    }
    __syncthreads();

    // ---- Q A-fragments (held in regs for whole kernel)
    uint32_t aq[4][4];
    {
        int r = w * 16 + (lane & 15);
        uint32_t base = uQ + (uint32_t)r * 128;
        uint32_t sw = (uint32_t)((r & 7) << 4);
        #pragma unroll
        for (int kk = 0; kk < 4; kk++) {
            uint32_t off = (uint32_t)(kk * 32 + (lane >> 4) * 16);
            ldsm4(aq[kk], base + (off ^ sw));
        }
    }

    float o[8][4];
    #pragma unroll
    for (int j = 0; j < 8; j++)
        #pragma unroll
        for (int c = 0; c < 4; c++) o[j][c] = 0.f;
    float mrow[2] = {-1e30f, -1e30f};
    float lrow[2] = {0.f, 0.f};

    const int g  = lane >> 2;
    const int tt = lane & 3;

    for (int kb = 0; kb <= qb; kb++) {
        __syncthreads();   // protect sK/sV reuse
        {
            int row = t >> 1;
            int cs  = (t & 1) * 4;
            const float* ks = Kp + ((size_t)(b * SEQ + kb * 64 + row)) * DMODEL + hoff + cs * 8;
            const float* vs = Vp + ((size_t)(b * SEQ + kb * 64 + row)) * DMODEL + hoff + cs * 8;
            uint32_t swz = (uint32_t)((row & 7) << 4);
            #pragma unroll
            for (int c = 0; c < 4; c++) {
                float4 f0 = *(const float4*)(ks + c * 8);
                float4 f1 = *(const float4*)(ks + c * 8 + 4);
                uint4 u = { packhf(f0.x, f0.y), packhf(f0.z, f0.w),
                            packhf(f1.x, f1.y), packhf(f1.z, f1.w) };
                *(uint4*)(sK + row * 128 + ((uint32_t)((cs + c) * 16) ^ swz)) = u;
                float4 g0 = *(const float4*)(vs + c * 8);
                float4 g1 = *(const float4*)(vs + c * 8 + 4);
                uint4 v = { packhf(g0.x, g0.y), packhf(g0.z, g0.w),
                            packhf(g1.x, g1.y), packhf(g1.z, g1.w) };
                *(uint4*)(sV + row * 128 + ((uint32_t)((cs + c) * 16) ^ swz)) = v;
            }
        }
        __syncthreads();

        // ---- scores S = Q*K^T (scaled already)
        float sc[8][4];
        #pragma unroll
        for (int j = 0; j < 8; j++)
            #pragma unroll
            for (int c = 0; c < 4; c++) sc[j][c] = 0.f;

        #pragma unroll
        for (int j = 0; j < 8; j++) {
            uint32_t base = uK + (uint32_t)(j * 8 + (lane & 7)) * 128;
            uint32_t sw = (uint32_t)((lane & 7) << 4);
            #pragma unroll
            for (int kk = 0; kk < 4; kk++) {
                uint32_t bk[2];
                uint32_t off = (uint32_t)(kk * 32 + ((lane >> 3) & 1) * 16);
                ldsm2(bk, base + (off ^ sw));
                mma_hf(sc[j], aq[kk], bk);
            }
        }

        // ---- causal mask on diagonal block
        if (kb == qb) {
            #pragma unroll
            for (int j = 0; j < 8; j++) {
                int colb = kb * 64 + j * 8 + 2 * tt;
                int r0 = q0 + w * 16 + g;
                if (colb     > r0)     sc[j][0] = -1e30f;
                if (colb + 1 > r0)     sc[j][1] = -1e30f;
                if (colb     > r0 + 8) sc[j][2] = -1e30f;
                if (colb + 1 > r0 + 8) sc[j][3] = -1e30f;
            }
        }

        // ---- online softmax (two row-halves per thread)
        #pragma unroll
        for (int rh = 0; rh < 2; rh++) {
            float m = -1e30f;
            #pragma unroll
            for (int j = 0; j < 8; j++)
                m = fmaxf(m, fmaxf(sc[j][2 * rh], sc[j][2 * rh + 1]));
            m = fmaxf(m, __shfl_xor_sync(0xffffffffu, m, 1));
            m = fmaxf(m, __shfl_xor_sync(0xffffffffu, m, 2));
            float mnew = fmaxf(mrow[rh], m);
            float scal = __expf(mrow[rh] - mnew);
            mrow[rh] = mnew;
            float rs = 0.f;
            #pragma unroll
            for (int j = 0; j < 8; j++) {
                float e0 = __expf(sc[j][2 * rh]     - mnew);
                float e1 = __expf(sc[j][2 * rh + 1] - mnew);
                sc[j][2 * rh] = e0; sc[j][2 * rh + 1] = e1;
                rs += e0 + e1;
            }
            rs += __shfl_xor_sync(0xffffffffu, rs, 1);
            rs += __shfl_xor_sync(0xffffffffu, rs, 2);
            lrow[rh] = lrow[rh] * scal + rs;
            #pragma unroll
            for (int j = 0; j < 8; j++) {
                o[j][2 * rh]     *= scal;
                o[j][2 * rh + 1] *= scal;
            }
        }

        // ---- O += P * V  (P from score c-frags, V via ldmatrix.trans)
        #pragma unroll
        for (int kk = 0; kk < 4; kk++) {
            uint32_t pa[4];
            pa[0] = packhf(sc[2 * kk][0],     sc[2 * kk][1]);
            pa[1] = packhf(sc[2 * kk][2],     sc[2 * kk][3]);
            pa[2] = packhf(sc[2 * kk + 1][0], sc[2 * kk + 1][1]);
            pa[3] = packhf(sc[2 * kk + 1][2], sc[2 * kk + 1][3]);

            int rV = kk * 16 + ((lane >> 3) & 1) * 8 + (lane & 7);
            uint32_t baseV = uV + (uint32_t)rV * 128;
            uint32_t swV = (uint32_t)((rV & 7) << 4);
            #pragma unroll
            for (int j2 = 0; j2 < 4; j2++) {
                uint32_t bv[4];
                uint32_t off = (uint32_t)((j2 * 2 + (lane >> 4)) * 16);
                ldsm4t(bv, baseV + (off ^ swV));
                mma_hf(o[2 * j2],     pa, bv);
                mma_hf(o[2 * j2 + 1], pa, bv + 2);
            }
        }
    }

    // ---- normalize + store
    float inv0 = 1.f / lrow[0];
    float inv1 = 1.f / lrow[1];
    int r0 = q0 + w * 16 + g;
    float* out0 = Op + ((size_t)(b * SEQ + r0)) * DMODEL + hoff;
    float* out1 = Op + ((size_t)(b * SEQ + r0 + 8)) * DMODEL + hoff;
    #pragma unroll
    for (int j = 0; j < 8; j++) {
        int col = j * 8 + 2 * tt;
        float2 w0 = {o[j][0] * inv0, o[j][1] * inv0};
        float2 w1 = {o[j][2] * inv1, o[j][3] * inv1};
        *(float2*)(out0 + col) = w0;
        *(float2*)(out1 + col) = w1;
    }
}

// ---------------------------------------------------------------------------
// Launch
// ---------------------------------------------------------------------------
#define GEMM_SMEM (8 * GSTG)

extern "C" void kernel_launch(void* const* d_in, const int* in_sizes, int n_in,
                              void* d_out, int out_size)
{
    const float* x       = (const float*)d_in[0];
    const float* Wq      = (const float*)d_in[1];
    const float* Wk      = (const float*)d_in[2];
    const float* Wv      = (const float*)d_in[3];
    const float* Wo      = (const float*)d_in[4];
    const float* W_up    = (const float*)d_in[5];
    const float* W_down  = (const float*)d_in[6];
    const float* ln1_ms  = (const float*)d_in[7];
    const float* ln1_ss  = (const float*)d_in[8];
    const float* ln2_ms  = (const float*)d_in[9];
    const float* ln2_ss  = (const float*)d_in[10];
    float* out = (float*)d_out;

    float *xn, *qb, *kb, *vb, *attn, *x1, *mid;
    cudaGetSymbolAddress((void**)&xn,   g_xn);
    cudaGetSymbolAddress((void**)&qb,   g_q);
    cudaGetSymbolAddress((void**)&kb,   g_k);
    cudaGetSymbolAddress((void**)&vb,   g_v);
    cudaGetSymbolAddress((void**)&attn, g_attn);
    cudaGetSymbolAddress((void**)&x1,   g_x1);
    cudaGetSymbolAddress((void**)&mid,  g_mid);

    cudaFuncSetAttribute(gemm_mma<0>, cudaFuncAttributeMaxDynamicSharedMemorySize, GEMM_SMEM);
    cudaFuncSetAttribute(gemm_mma<1>, cudaFuncAttributeMaxDynamicSharedMemorySize, GEMM_SMEM);
    cudaFuncSetAttribute(gemm_mma<2>, cudaFuncAttributeMaxDynamicSharedMemorySize, GEMM_SMEM);

    // 1) LN1
    ln_kernel<<<MROWS, 256>>>(x, ln1_ms, ln1_ss, xn);

    // 2) Q,K,V projections
    dim3 gqkv(DMODEL / 128, MROWS / 128);
    gemm_mma<0><<<gqkv, 256, GEMM_SMEM>>>(xn, Wq, nullptr, qb, MROWS, DMODEL, DMODEL);
    gemm_mma<0><<<gqkv, 256, GEMM_SMEM>>>(xn, Wk, nullptr, kb, MROWS, DMODEL, DMODEL);
    gemm_mma<0><<<gqkv, 256, GEMM_SMEM>>>(xn, Wv, nullptr, vb, MROWS, DMODEL, DMODEL);

    // 3) causal attention (fp16 HMMA flash)
    attn_mma<<<dim3(SEQ / 64, BATCH * NHEADS), 128>>>(qb, kb, vb, attn);

    // 4) out projection + residual
    gemm_mma<2><<<gqkv, 256, GEMM_SMEM>>>(attn, Wo, x, x1, MROWS, DMODEL, DMODEL);

    // 5) LN2
    ln_kernel<<<MROWS, 256>>>(x1, ln2_ms, ln2_ss, xn);

    // 6) MLP up + exact gelu
    dim3 gup(DFF / 128, MROWS / 128);
    gemm_mma<1><<<gup, 256, GEMM_SMEM>>>(xn, W_up, nullptr, mid, MROWS, DFF, DMODEL);

    // 7) MLP down + residual
    dim3 gdown(DMODEL / 128, MROWS / 128);
    gemm_mma<2><<<gdown, 256, GEMM_SMEM>>>(mid, W_down, x1, out, MROWS, DMODEL, DFF);
}